// round 13
// baseline (speedup 1.0000x reference)
#include <cuda_runtime.h>
#include <cstdint>

// BorderLoss: mean( w * BCEwithlogits(x, y) ), w = 1 + border(y),
// border = 3x3dilate(y) & ~3x3erode(y), RATIO=2.
// x: [64,512,512] f32, y: [64,512,512] i32 in {0,1}. Output: 1 float.
//
// Identities:
//   loss = softplus((1-2y)*x)        (exact; |x|<~6 so no overflow guard needed)
//   erode = 3x3 AND, dilate = 3x3 OR (binary mask); bytes packed as {0,0x80}
//   w=2 on border == +1 to loss exponent (loss >= softplus(-6) ~ 2.5e-3, normal)
//   SAME padding == index clamp (idempotent duplicates under min/max)
//
// Round-12: measured matrix says the main loop runs 27.0-27.4us @ 43 regs
// (REDG-only epilogue) but 29.0-29.9us @ 36 regs whenever the ticket finalize
// is inlined into the kernel — the tail pollutes the hot loop's register
// allocation and load batching. Fix: ticket finalize in a __noinline__ device
// function (ABI boundary isolates codegen), keeping the single-graph-node
// launch shape that made R7 the bench winner.

static constexpr int W  = 512;
static constexpr int H  = 512;
static constexpr int NI = 64;
static constexpr int ROWS_PER_WARP = 8;      // block = 4 warps -> 32 rows
static constexpr int GRID = NI * (H / 32);   // 1024

__device__ float    g_part[GRID];
__device__ unsigned g_ticket = 0;

__device__ __noinline__ void finalize_reduce(float* __restrict__ out)
{
    __shared__ float fs[4];
    __shared__ int   f_last;
    const int lane = threadIdx.x & 31;
    const int warp = threadIdx.x >> 5;

    if (threadIdx.x == 0) {
        __threadfence();
        unsigned t = atomicAdd(&g_ticket, 1u);
        f_last = (t == (unsigned)(GRID - 1));
    }
    __syncthreads();
    if (!f_last) return;

    float v = 0.0f;
    for (int i = threadIdx.x; i < GRID; i += 128)
        v += __ldcg(&g_part[i]);
#pragma unroll
    for (int o = 16; o; o >>= 1)
        v += __shfl_down_sync(0xffffffffu, v, o);
    if (lane == 0) fs[warp] = v;
    __syncthreads();
    if (threadIdx.x == 0) {
        *out = ((fs[0] + fs[1]) + (fs[2] + fs[3])) * (1.0f / 16777216.0f);
        g_ticket = 0;   // reset for next graph replay
    }
}

__global__ __launch_bounds__(128)
void border_loss_kernel(const float* __restrict__ x,
                        const int*   __restrict__ y,
                        float* __restrict__ out)
{
    const int img   = blockIdx.x >> 4;     // 16 strips of 32 rows per image
    const int strip = blockIdx.x & 15;
    const int warp  = threadIdx.x >> 5;
    const int lane  = threadIdx.x & 31;
    const int row0  = strip * 32 + warp * ROWS_PER_WARP;
    const int col0  = lane * 16;           // 16 px/lane, 32 lanes = 512 cols

    const size_t imgoff = (size_t)img * H * W;
    const float* xbase = x + imgoff + (size_t)row0 * W + col0;
    const int*   ybase = y + imgoff + col0;

    // Packed mask rows: 4 regs x 4 bytes, byte value in {0, 0x80}
    unsigned pm[4], cm[4], nm[4];

    auto loadm = [&](int g, unsigned m[4]) {
        const int4* p = (const int4*)(ybase + (size_t)g * W);
#pragma unroll
        for (int j = 0; j < 4; j++) {
            int4 v = p[j];
            unsigned p01 = __byte_perm((unsigned)v.x, (unsigned)v.y, 0x0040);
            unsigned p23 = __byte_perm((unsigned)v.z, (unsigned)v.w, 0x0040);
            m[j] = __byte_perm(p01, p23, 0x5410) << 7;   // each byte: y<<7
        }
    };

    loadm(row0 == 0 ? 0 : row0 - 1, pm);   // top clamp (idempotent for min/max)
    loadm(row0, cm);

    float acc = 0.0f;

#pragma unroll
    for (int r = 0; r < ROWS_PER_WARP; r++) {
        const int g = row0 + r;
        if (g + 1 < H) {
            loadm(g + 1, nm);
        } else {
#pragma unroll
            for (int j = 0; j < 4; j++) nm[j] = cm[j];   // bottom clamp
        }

        // Vertical 3-tap: AND = min, OR = max (bytes in {0,0x80})
        unsigned vmn[4], vmx[4];
#pragma unroll
        for (int j = 0; j < 4; j++) {
            vmn[j] = pm[j] & cm[j] & nm[j];
            vmx[j] = pm[j] | cm[j] | nm[j];
        }

        // Cross-lane halo: pack (min,max) edge bytes, one shfl each direction.
        unsigned el = __byte_perm(vmn[0], vmx[0], 0x0040); // b0=mn.b0, b1=mx.b0
        unsigned eh = __byte_perm(vmn[3], vmx[3], 0x0073); // b0=mn.b3, b1=mx.b3
        unsigned fromL = __shfl_up_sync(0xffffffffu, eh, 1);
        unsigned fromR = __shfl_down_sync(0xffffffffu, el, 1);
        if (lane == 0)  fromL = el;   // col clamp: duplicate own col 0
        if (lane == 31) fromR = eh;   // col clamp: duplicate own col 511

        unsigned border[4];
#pragma unroll
        for (int j = 0; j < 4; j++) {
            unsigned Lmn = (j == 0) ? __byte_perm(vmn[0], fromL, 0x2104)
                                    : __byte_perm(vmn[j], vmn[j-1], 0x2107);
            unsigned Lmx = (j == 0) ? __byte_perm(vmx[0], fromL, 0x2105)
                                    : __byte_perm(vmx[j], vmx[j-1], 0x2107);
            unsigned Rmn = (j == 3) ? __byte_perm(vmn[3], fromR, 0x4321)
                                    : __byte_perm(vmn[j], vmn[j+1], 0x4321);
            unsigned Rmx = (j == 3) ? __byte_perm(vmx[3], fromR, 0x5321)
                                    : __byte_perm(vmx[j], vmx[j+1], 0x4321);
            // border byte = dilate & ~erode, values in {0, 0x80}
            border[j] = (vmx[j] | Lmx | Rmx) & ~(vmn[j] & Lmn & Rmn);
        }

        // Loss + weight + accumulate
        const float4* xr = (const float4*)(xbase + (size_t)r * W);
#pragma unroll
        for (int j = 0; j < 4; j++) {
            float4 xv = xr[j];
            float xsv[4] = {xv.x, xv.y, xv.z, xv.w};
#pragma unroll
            for (int i = 0; i < 4; i++) {
                // sign: 0x80000000 iff y==1 (cm byte i == 0x80)
                unsigned sgn = __byte_perm(cm[j], 0u, 0x0444 | (i << 12));
                float z = __int_as_float(__float_as_int(xsv[i]) ^ sgn);
                float l = __logf(1.0f + __expf(z));     // softplus, z in [-6,6]
                // weight: +0x00800000 (exponent +1) iff border
                unsigned wb = __byte_perm(border[j], 0u, 0x4044 | (i << 8));
                acc += __int_as_float(__float_as_int(l) + wb);
            }
        }

        // rotate rows
#pragma unroll
        for (int j = 0; j < 4; j++) { pm[j] = cm[j]; cm[j] = nm[j]; }
    }

    // ---- block reduce: warp shfl, 4 partials via smem, one STG per block ----
#pragma unroll
    for (int o = 16; o; o >>= 1)
        acc += __shfl_down_sync(0xffffffffu, acc, o);

    __shared__ float ws[4];
    if (lane == 0) ws[warp] = acc;
    __syncthreads();
    if (threadIdx.x == 0)
        g_part[blockIdx.x] = (ws[0] + ws[1]) + (ws[2] + ws[3]);

    // ---- ticket finalize, codegen-isolated behind an ABI boundary ----
    finalize_reduce(out);
}

extern "C" void kernel_launch(void* const* d_in, const int* in_sizes, int n_in,
                              void* d_out, int out_size)
{
    const float* x = (const float*)d_in[0];
    const int*   y = (const int*)d_in[1];
    float* out = (float*)d_out;

    border_loss_kernel<<<GRID, 128>>>(x, y, out);
}

// round 14
// speedup vs baseline: 1.1337x; 1.1337x over previous
#include <cuda_runtime.h>
#include <cstdint>

// BorderLoss: mean( w * BCEwithlogits(x, y) ), w = 1 + border(y),
// border = 3x3dilate(y) & ~3x3erode(y), RATIO=2.
// x: [64,512,512] f32, y: [64,512,512] i32 in {0,1}. Output: 1 float.
//
// Identities:
//   loss = softplus((1-2y)*x)        (exact; |x|<~6 so no overflow guard needed)
//   erode = 3x3 AND, dilate = 3x3 OR (binary mask)
//   w=2 on border == +1 to loss exponent (loss >= softplus(-6) ~ 2.5e-3, normal)
//   SAME padding == index clamp (idempotent duplicates under min/max)
//
// Round-14: two-pass, stencil in the compressed domain.
//   K1: pure stream pack — y (64MB) -> 1 bit/px (2MB device buffer). No halo,
//       no stencil: gelu-shaped stream. Also zeroes *out.
//   K2: R1's proven x-streaming loop (16 px/lane, 8 rows/warp, grid 1024,
//       plain float4 loads, per-block atomicAdd epilogue = the one epilogue
//       that keeps 43-reg codegen) with the 3x3 stencil on BIT rows: one
//       LDG.U16 per row instead of 4x LDG.128. y halo re-reads now hit a 2MB
//       L2-resident buffer instead of DRAM.
// DRAM: ~66MB + ~66MB, both simple streams, vs 150MB fused.

static constexpr int W  = 512;
static constexpr int H  = 512;
static constexpr int NI = 64;
static constexpr int ROWS_PER_WARP = 8;       // K2: block = 4 warps -> 32 rows
static constexpr int GRID2 = NI * (H / 32);   // 1024
static constexpr int NPACK = NI * H * W / 32; // 524288 u32 = 2MB

__device__ unsigned g_bits[NPACK];

// ---------------- K1: pack y -> bits (1 bit per px), zero out ----------------
__global__ __launch_bounds__(256)
void pack_kernel(const int* __restrict__ y, float* __restrict__ out)
{
    const int t = blockIdx.x * 256 + threadIdx.x;   // one u32 (32 px) per thread
    if (t == 0) *out = 0.0f;

    const int4* p = (const int4*)y + (size_t)t * 8;
    unsigned bits = 0;
#pragma unroll
    for (int j = 0; j < 8; j++) {
        int4 v = p[j];
        // gather low bytes of 4 ints -> 4 bytes, <<7 => bytes in {0,0x80}
        unsigned p01 = __byte_perm((unsigned)v.x, (unsigned)v.y, 0x0040);
        unsigned p23 = __byte_perm((unsigned)v.z, (unsigned)v.w, 0x0040);
        unsigned m   = __byte_perm(p01, p23, 0x5410) << 7;
        // movemask: bits {7,15,23,31} -> nibble (px0 at bit0)
        unsigned nib = ((m & 0x80808080u) * 0x00204081u) >> 28;
        bits |= nib << (4 * j);
    }
    g_bits[t] = bits;
}

// ---------------- K2: stencil on bits + BCE loss + reduce ----------------
__global__ __launch_bounds__(128)
void border_loss_kernel(const float* __restrict__ x, float* __restrict__ out)
{
    const int img   = blockIdx.x >> 4;     // 16 strips of 32 rows per image
    const int strip = blockIdx.x & 15;
    const int warp  = threadIdx.x >> 5;
    const int lane  = threadIdx.x & 31;
    const int row0  = strip * 32 + warp * ROWS_PER_WARP;
    const int col0  = lane * 16;           // 16 px/lane, 32 lanes = 512 cols

    const float* xbase = x + (size_t)img * H * W + (size_t)row0 * W + col0;
    // bit rows: 32 ushorts per row; lane's 16 px = ushort at [row*32 + lane]
    const unsigned short* brow =
        (const unsigned short*)g_bits + (size_t)img * H * 32 + lane;

    auto ldb = [&](int g) -> unsigned { return brow[(size_t)g * 32]; };

    unsigned pm = ldb(row0 == 0 ? 0 : row0 - 1);   // top clamp
    unsigned cm = ldb(row0);

    float acc = 0.0f;

#pragma unroll
    for (int r = 0; r < ROWS_PER_WARP; r++) {
        const int g = row0 + r;
        unsigned nm = (g + 1 < H) ? ldb(g + 1) : cm;   // bottom clamp

        // Vertical 3-tap on 16-bit rows: AND = erode, OR = dilate
        const unsigned vmn = pm & cm & nm;
        const unsigned vmx = pm | cm | nm;

        // Horizontal halo bits across lanes: pack (mn | mx<<16), 2 shfls.
        const unsigned pk = vmn | (vmx << 16);
        const unsigned eL = __shfl_up_sync(0xffffffffu, pk, 1);
        const unsigned eR = __shfl_down_sync(0xffffffffu, pk, 1);
        unsigned lmn, lmx, rmn, rmx;
        if (lane == 0) { lmn = vmn & 1u;         lmx = vmx & 1u; }          // col clamp
        else           { lmn = (eL >> 15) & 1u;  lmx = eL >> 31; }
        if (lane == 31){ rmn = (vmn >> 15) & 1u; rmx = (vmx >> 15) & 1u; }  // col clamp
        else           { rmn = eR & 1u;          rmx = (eR >> 16) & 1u; }

        const unsigned Lmn = (vmn << 1) | lmn;
        const unsigned Lmx = (vmx << 1) | lmx;
        const unsigned Rmn = (vmn >> 1) | (rmn << 15);
        const unsigned Rmx = (vmx >> 1) | (rmx << 15);

        // border bit i = dilate & ~erode (bits >=16 are garbage; masked on use)
        const unsigned border = (vmx | Lmx | Rmx) & ~(vmn & Lmn & Rmn);

        // Loss + weight + accumulate (x streamed exactly as the proven loop)
        const float4* xr = (const float4*)(xbase + (size_t)r * W);
#pragma unroll
        for (int j = 0; j < 4; j++) {
            float4 xv = xr[j];
            float xsv[4] = {xv.x, xv.y, xv.z, xv.w};
#pragma unroll
            for (int i = 0; i < 4; i++) {
                const int k = j * 4 + i;     // px index 0..15, bit k of cm/border
                // sign: y bit k -> bit31, fused xor
                unsigned s = cm << (31 - k);
                float z = __int_as_float(__float_as_int(xsv[i]) ^ (s & 0x80000000u));
                float l = __logf(1.0f + __expf(z));   // softplus, z in [-6,6]
                // weight: border bit k -> +0x00800000 (exponent +1, exact *2)
                unsigned wb = (border << (23 - k)) & 0x00800000u;
                acc += __int_as_float(__float_as_int(l) + wb);
            }
        }

        pm = cm; cm = nm;   // rotate rows
    }

    // ---- block reduce: warp shfl, 4 partials via smem, one REDG per block ----
#pragma unroll
    for (int o = 16; o; o >>= 1)
        acc += __shfl_down_sync(0xffffffffu, acc, o);

    __shared__ float ws[4];
    if (lane == 0) ws[warp] = acc;
    __syncthreads();
    if (threadIdx.x == 0) {
        float s = (ws[0] + ws[1]) + (ws[2] + ws[3]);
        atomicAdd(out, s * (1.0f / 16777216.0f));   // return unused -> REDG
    }
}

extern "C" void kernel_launch(void* const* d_in, const int* in_sizes, int n_in,
                              void* d_out, int out_size)
{
    const float* x = (const float*)d_in[0];
    const int*   y = (const int*)d_in[1];
    float* out = (float*)d_out;

    pack_kernel<<<NPACK / 256, 256>>>(y, out);      // also zeroes *out
    border_loss_kernel<<<GRID2, 128>>>(x, out);
}

// round 15
// speedup vs baseline: 1.4431x; 1.2729x over previous
#include <cuda_runtime.h>
#include <cstdint>

// BorderLoss: mean( w * BCEwithlogits(x, y) ), w = 1 + border(y),
// border = 3x3dilate(y) & ~3x3erode(y), RATIO=2.
// x: [64,512,512] f32, y: [64,512,512] i32 in {0,1}. Output: 1 float.
//
// Identities:
//   loss = softplus((1-2y)*x)        (exact; |x|<~6 so no overflow guard needed)
//   erode = 3x3 AND, dilate = 3x3 OR (binary mask)
//   w=2 on border == +1 to loss exponent (loss >= softplus(-6) ~ 2.5e-3, normal)
//   SAME padding == index clamp (idempotent duplicates under min/max)
//
// Round-15: single kernel, stencil in the compressed domain (R14's K2 proved
// the bit-stencil at 16.1us), with the pack fused as a smem phase:
//   Phase A: block packs its 32 rows + 2 halo rows of y into 34x64B smem bits
//            (dense int4 burst, ~17 loads/thread, high MLP).
//   Phase B: per warp 4 rows; bit rows from smem (LDS.U16, zero global y,
//            zero conditionals), x streamed as 4x LDG.128/row. 2 accumulators.
// Traffic: 68MB y + 64MB x = 132MB, one kernel node + one memset node
// (R9 measured the memset-node epilogue at ~1us total overhead; in-kernel
// ticket tails wreck hot-loop codegen per R11-R13).

static constexpr int W  = 512;
static constexpr int H  = 512;
static constexpr int NI = 64;
static constexpr int ROWS_PER_BLOCK = 32;            // 8 warps x 4 rows
static constexpr int GRID = NI * (H / ROWS_PER_BLOCK);  // 1024

__global__ __launch_bounds__(256)
void border_loss_kernel(const float* __restrict__ x,
                        const int*   __restrict__ y,
                        float* __restrict__ out)
{
    const int img      = blockIdx.x >> 4;    // 16 strips of 32 rows per image
    const int strip    = blockIdx.x & 15;
    const int row_base = strip * 32;
    const int warp     = threadIdx.x >> 5;   // 0..7
    const int lane     = threadIdx.x & 31;

    const size_t imgoff = (size_t)img * H * W;

    // ---- Phase A: pack y rows [row_base-1, row_base+32] (clamped) to bits ----
    // sbits[rr][bc] byte = y pixels [bc*8 .. bc*8+7] of global row row_base-1+rr.
    __shared__ unsigned char sbits[34][64];          // 2176 B

    for (int b = threadIdx.x; b < 34 * 64; b += 256) {
        const int rr = b >> 6;          // 0..33
        const int bc = b & 63;
        int gr = row_base - 1 + rr;
        gr = (gr < 0) ? 0 : (gr >= H ? H - 1 : gr);  // SAME-pad clamp
        const int4* p = (const int4*)(y + imgoff + (size_t)gr * W + bc * 8);
        int4 v0 = p[0], v1 = p[1];
        unsigned m0 = __byte_perm(__byte_perm((unsigned)v0.x, (unsigned)v0.y, 0x0040),
                                  __byte_perm((unsigned)v0.z, (unsigned)v0.w, 0x0040),
                                  0x5410) << 7;
        unsigned m1 = __byte_perm(__byte_perm((unsigned)v1.x, (unsigned)v1.y, 0x0040),
                                  __byte_perm((unsigned)v1.z, (unsigned)v1.w, 0x0040),
                                  0x5410) << 7;
        unsigned nib0 = ((m0 & 0x80808080u) * 0x00204081u) >> 28;  // px0 -> bit0
        unsigned nib1 = ((m1 & 0x80808080u) * 0x00204081u) >> 28;
        sbits[rr][bc] = (unsigned char)(nib0 | (nib1 << 4));
    }
    __syncthreads();

    // ---- Phase B: stencil on smem bits + BCE loss on streamed x ----
    const int lr0 = warp * 4;                        // sbits row of top halo
    const float* xbase = x + imgoff + (size_t)(row_base + warp * 4) * W + lane * 16;
    const unsigned short* srow = (const unsigned short*)sbits;  // 32 u16 per row

    unsigned pm = srow[(lr0 + 0) * 32 + lane];
    unsigned cm = srow[(lr0 + 1) * 32 + lane];

    float acc0 = 0.0f, acc1 = 0.0f;

#pragma unroll
    for (int r = 0; r < 4; r++) {
        unsigned nm = srow[(lr0 + 2 + r) * 32 + lane];

        // Vertical 3-tap on 16-bit rows: AND = erode, OR = dilate
        const unsigned vmn = pm & cm & nm;
        const unsigned vmx = pm | cm | nm;

        // Horizontal halo bits across lanes: pack (mn | mx<<16), 2 shfls.
        const unsigned pk = vmn | (vmx << 16);
        const unsigned eL = __shfl_up_sync(0xffffffffu, pk, 1);
        const unsigned eR = __shfl_down_sync(0xffffffffu, pk, 1);
        unsigned lmn, lmx, rmn, rmx;
        if (lane == 0) { lmn = vmn & 1u;         lmx = vmx & 1u; }          // col clamp
        else           { lmn = (eL >> 15) & 1u;  lmx = eL >> 31; }
        if (lane == 31){ rmn = (vmn >> 15) & 1u; rmx = (vmx >> 15) & 1u; }  // col clamp
        else           { rmn = eR & 1u;          rmx = (eR >> 16) & 1u; }

        const unsigned Lmn = (vmn << 1) | lmn;
        const unsigned Lmx = (vmx << 1) | lmx;
        const unsigned Rmn = (vmn >> 1) | (rmn << 15);
        const unsigned Rmx = (vmx >> 1) | (rmx << 15);

        // border bit k = dilate & ~erode (bits >=16 garbage; masked on use)
        const unsigned border = (vmx | Lmx | Rmx) & ~(vmn & Lmn & Rmn);

        // Loss + weight + accumulate
        const float4* xr = (const float4*)(xbase + (size_t)r * W);
#pragma unroll
        for (int j = 0; j < 4; j++) {
            float4 xv = xr[j];
            float xsv[4] = {xv.x, xv.y, xv.z, xv.w};
#pragma unroll
            for (int i = 0; i < 4; i++) {
                const int k = j * 4 + i;     // px index 0..15 = bit k
                unsigned s = cm << (31 - k);                 // y bit -> sign bit
                float z = __int_as_float(__float_as_int(xsv[i]) ^ (s & 0x80000000u));
                float l = __logf(1.0f + __expf(z));          // softplus, z in [-6,6]
                unsigned wb = (border << (23 - k)) & 0x00800000u;  // exact *2 on border
                float term = __int_as_float(__float_as_int(l) + wb);
                if (i & 1) acc1 += term; else acc0 += term;  // 2 chains
            }
        }

        pm = cm; cm = nm;   // rotate rows
    }

    float acc = acc0 + acc1;

    // ---- block reduce: warp shfl, 8 partials via smem, one REDG per block ----
#pragma unroll
    for (int o = 16; o; o >>= 1)
        acc += __shfl_down_sync(0xffffffffu, acc, o);

    __shared__ float ws[8];
    if (lane == 0) ws[warp] = acc;
    __syncthreads();
    if (threadIdx.x == 0) {
        float s = ((ws[0] + ws[1]) + (ws[2] + ws[3]))
                + ((ws[4] + ws[5]) + (ws[6] + ws[7]));
        atomicAdd(out, s * (1.0f / 16777216.0f));   // return unused -> REDG
    }
}

extern "C" void kernel_launch(void* const* d_in, const int* in_sizes, int n_in,
                              void* d_out, int out_size)
{
    const float* x = (const float*)d_in[0];
    const int*   y = (const int*)d_in[1];
    float* out = (float*)d_out;

    cudaMemsetAsync(out, 0, sizeof(float));          // ~1us node (R9 measured)
    border_loss_kernel<<<GRID, 256>>>(x, y, out);
}